// round 5
// baseline (speedup 1.0000x reference)
#include <cuda_runtime.h>

#define N_NODES 50000
#define N_EDGES 800000
#define IN_F 256
#define HID 128
#define OUT_F 64
#define ATTN_SLOPE 0.2f
#define ACT_SLOPE 0.01f
#define NEG_BIG -1.0e30f
#define FULLMASK 0xFFFFFFFFu

// -------- scratch (device globals; no allocation allowed) --------
__device__ float g_feat[N_NODES * HID];
__device__ float g_el[N_NODES];
__device__ float g_er[N_NODES];
__device__ float g_alpha[N_EDGES];     // normalized attention per CSR slot
__device__ float g_agg[N_NODES * HID];
__device__ float g_wl[IN_F];           // W_gat @ attn_l
__device__ float g_wr[IN_F];           // W_gat @ attn_r
__device__ int   g_cnt[N_NODES];
__device__ int   g_row[N_NODES + 1];
__device__ int   g_cursor[N_NODES];
__device__ int   g_csr_src[N_EDGES];

// ================= zero the histogram =================
__global__ void init_cnt_kernel() {
    int tid = blockIdx.x * blockDim.x + threadIdx.x;
    int stride = gridDim.x * blockDim.x;
    for (int i = tid; i < N_NODES; i += stride) g_cnt[i] = 0;
}

// ================= histogram of dst =================
__global__ __launch_bounds__(256) void hist_kernel(const int* __restrict__ dst) {
    int i = blockIdx.x * blockDim.x + threadIdx.x;
    if (i < N_EDGES) atomicAdd(&g_cnt[dst[i]], 1);
}

// ================= single-block exclusive scan over 50000 counts =================
__global__ __launch_bounds__(1024) void scan_kernel() {
    __shared__ int sm[1024];
    const int CH = (N_NODES + 1023) / 1024;  // 49
    int tid = threadIdx.x;
    int base = tid * CH;
    int local[49];
    int sum = 0;
#pragma unroll
    for (int j = 0; j < CH; j++) {
        int idx = base + j;
        int c = (idx < N_NODES) ? g_cnt[idx] : 0;
        local[j] = c;
        sum += c;
    }
    sm[tid] = sum;
    __syncthreads();
    for (int off = 1; off < 1024; off <<= 1) {
        int v = sm[tid];
        if (tid >= off) v += sm[tid - off];
        __syncthreads();
        sm[tid] = v;
        __syncthreads();
    }
    int run = (tid > 0) ? sm[tid - 1] : 0;
#pragma unroll
    for (int j = 0; j < CH; j++) {
        int idx = base + j;
        if (idx < N_NODES) {
            g_row[idx] = run;
            g_cursor[idx] = run;
            run += local[j];
        }
    }
    if (tid == 1023) g_row[N_NODES] = N_EDGES;
}

// ================= scatter edges into CSR buckets =================
__global__ __launch_bounds__(256) void scatter_kernel(
    const int* __restrict__ src, const int* __restrict__ dst) {
    int i = blockIdx.x * blockDim.x + threadIdx.x;
    if (i >= N_EDGES) return;
    int d = dst[i];
    int pos = atomicAdd(&g_cursor[d], 1);
    g_csr_src[pos] = src[i];
}

// ================= w_l = W_gat @ attn_l, w_r = W_gat @ attn_r =================
// one warp per k-row of W_gat (256 rows x 128), lane handles 4 h.
__global__ __launch_bounds__(256) void wlr_kernel(
    const float* __restrict__ W, const float* __restrict__ al,
    const float* __restrict__ ar) {
    int k = (blockIdx.x * blockDim.x + threadIdx.x) >> 5;
    int lane = threadIdx.x & 31;
    if (k >= IN_F) return;
    float4 w = *reinterpret_cast<const float4*>(&W[k * HID + lane * 4]);
    float4 a = *reinterpret_cast<const float4*>(&al[lane * 4]);
    float4 b = *reinterpret_cast<const float4*>(&ar[lane * 4]);
    float sl = w.x * a.x + w.y * a.y + w.z * a.z + w.w * a.w;
    float sr = w.x * b.x + w.y * b.y + w.z * b.z + w.w * b.w;
#pragma unroll
    for (int o = 16; o > 0; o >>= 1) {
        sl += __shfl_down_sync(FULLMASK, sl, o);
        sr += __shfl_down_sync(FULLMASK, sr, o);
    }
    if (lane == 0) {
        g_wl[k] = sl;
        g_wr[k] = sr;
    }
}

// ================= el[n] = x[n,:] . w_l, er[n] = x[n,:] . w_r =================
// one warp per node; lane owns 8 consecutive floats (2 x float4).
__global__ __launch_bounds__(256) void elr_kernel(const float* __restrict__ x) {
    int n = (blockIdx.x * blockDim.x + threadIdx.x) >> 5;
    int lane = threadIdx.x & 31;
    if (n >= N_NODES) return;
    const float4* xr = reinterpret_cast<const float4*>(&x[n * IN_F]);
    float4 x0 = xr[lane * 2];
    float4 x1 = xr[lane * 2 + 1];
    float4 l0 = *reinterpret_cast<const float4*>(&g_wl[lane * 8]);
    float4 l1 = *reinterpret_cast<const float4*>(&g_wl[lane * 8 + 4]);
    float4 r0 = *reinterpret_cast<const float4*>(&g_wr[lane * 8]);
    float4 r1 = *reinterpret_cast<const float4*>(&g_wr[lane * 8 + 4]);
    float sl = x0.x * l0.x + x0.y * l0.y + x0.z * l0.z + x0.w * l0.w
             + x1.x * l1.x + x1.y * l1.y + x1.z * l1.z + x1.w * l1.w;
    float sr = x0.x * r0.x + x0.y * r0.y + x0.z * r0.z + x0.w * r0.w
             + x1.x * r1.x + x1.y * r1.y + x1.z * r1.z + x1.w * r1.w;
#pragma unroll
    for (int o = 16; o > 0; o >>= 1) {
        sl += __shfl_down_sync(FULLMASK, sl, o);
        sr += __shfl_down_sync(FULLMASK, sr, o);
    }
    if (lane == 0) {
        g_el[n] = sl;
        g_er[n] = sr;
    }
}

// ================= per-node edge softmax: write normalized alpha per CSR slot =================
__global__ __launch_bounds__(256) void edge_softmax_kernel() {
    int node = (blockIdx.x * blockDim.x + threadIdx.x) >> 5;
    int lane = threadIdx.x & 31;
    if (node >= N_NODES) return;
    int start = g_row[node];
    int deg = g_row[node + 1] - start;
    if (deg == 0) return;
    float er_d = g_er[node];
    if (deg <= 32) {
        float e = NEG_BIG;
        if (lane < deg) {
            int sidx = g_csr_src[start + lane];
            float v = g_el[sidx] + er_d;
            e = (v > 0.f) ? v : ATTN_SLOPE * v;
        }
        float m = e;
#pragma unroll
        for (int o = 16; o > 0; o >>= 1)
            m = fmaxf(m, __shfl_xor_sync(FULLMASK, m, o));
        float p = (lane < deg) ? __expf(e - m) : 0.f;
        float s = p;
#pragma unroll
        for (int o = 16; o > 0; o >>= 1)
            s += __shfl_xor_sync(FULLMASK, s, o);
        if (lane < deg) g_alpha[start + lane] = p / s;
    } else {
        int end = start + deg;
        float m = NEG_BIG, s = 0.f;
        for (int i = start + lane; i < end; i += 32) {
            int sx = g_csr_src[i];
            float v = g_el[sx] + er_d;
            float e = (v > 0.f) ? v : ATTN_SLOPE * v;
            float nm = fmaxf(m, e);
            s = s * __expf(m - nm) + __expf(e - nm);
            m = nm;
        }
#pragma unroll
        for (int o = 16; o > 0; o >>= 1) {
            float mo = __shfl_xor_sync(FULLMASK, m, o);
            float so = __shfl_xor_sync(FULLMASK, s, o);
            float nm = fmaxf(m, mo);
            s = s * __expf(m - nm) + so * __expf(mo - nm);
            m = nm;
        }
        float inv = 1.f / s;
        for (int i = start + lane; i < end; i += 32) {
            int sx = g_csr_src[i];
            float v = g_el[sx] + er_d;
            float e = (v > 0.f) ? v : ATTN_SLOPE * v;
            g_alpha[i] = __expf(e - m) * inv;
        }
    }
}

// ================= GEMM1: feat = x @ W_gat (no attn epilogue) =================
__global__ __launch_bounds__(256) void gemm_feat_kernel(
    const float* __restrict__ x, const float* __restrict__ W) {
    __shared__ __align__(16) float As[2][8][132];
    __shared__ __align__(16) float Bs[2][8][128];
    const int m0 = blockIdx.x * 128;
    const int tid = threadIdx.x;
    const int tx = tid & 15;
    const int ty = tid >> 4;
    const int arow = tid >> 1;
    const int ac4  = tid & 1;
    const int brow = tid >> 5;
    const int bc4  = tid & 31;

    float4 a_reg, b_reg;
    {
        int gm = m0 + arow;
        a_reg = (gm < N_NODES)
            ? *reinterpret_cast<const float4*>(&x[gm * IN_F + ac4 * 4])
            : make_float4(0.f, 0.f, 0.f, 0.f);
        b_reg = *reinterpret_cast<const float4*>(&W[brow * HID + bc4 * 4]);
    }
    As[0][ac4 * 4 + 0][arow] = a_reg.x;
    As[0][ac4 * 4 + 1][arow] = a_reg.y;
    As[0][ac4 * 4 + 2][arow] = a_reg.z;
    As[0][ac4 * 4 + 3][arow] = a_reg.w;
    *reinterpret_cast<float4*>(&Bs[0][brow][bc4 * 4]) = b_reg;
    __syncthreads();

    float acc[8][8];
#pragma unroll
    for (int i = 0; i < 8; i++)
#pragma unroll
        for (int j = 0; j < 8; j++) acc[i][j] = 0.f;

    int cur = 0;
    for (int t = 0; t < IN_F / 8; ++t) {
        if (t + 1 < IN_F / 8) {
            int k0 = (t + 1) * 8;
            int gm = m0 + arow;
            a_reg = (gm < N_NODES)
                ? *reinterpret_cast<const float4*>(&x[gm * IN_F + k0 + ac4 * 4])
                : make_float4(0.f, 0.f, 0.f, 0.f);
            b_reg = *reinterpret_cast<const float4*>(&W[(k0 + brow) * HID + bc4 * 4]);
        }
#pragma unroll
        for (int k = 0; k < 8; ++k) {
            float a[8], b[8];
            *reinterpret_cast<float4*>(&a[0]) =
                *reinterpret_cast<const float4*>(&As[cur][k][ty * 4]);
            *reinterpret_cast<float4*>(&a[4]) =
                *reinterpret_cast<const float4*>(&As[cur][k][64 + ty * 4]);
            *reinterpret_cast<float4*>(&b[0]) =
                *reinterpret_cast<const float4*>(&Bs[cur][k][tx * 4]);
            *reinterpret_cast<float4*>(&b[4]) =
                *reinterpret_cast<const float4*>(&Bs[cur][k][64 + tx * 4]);
#pragma unroll
            for (int i = 0; i < 8; i++)
#pragma unroll
                for (int j = 0; j < 8; j++) acc[i][j] += a[i] * b[j];
        }
        if (t + 1 < IN_F / 8) {
            int nxt = cur ^ 1;
            As[nxt][ac4 * 4 + 0][arow] = a_reg.x;
            As[nxt][ac4 * 4 + 1][arow] = a_reg.y;
            As[nxt][ac4 * 4 + 2][arow] = a_reg.z;
            As[nxt][ac4 * 4 + 3][arow] = a_reg.w;
            *reinterpret_cast<float4*>(&Bs[nxt][brow][bc4 * 4]) = b_reg;
            __syncthreads();
            cur = nxt;
        }
    }
#pragma unroll
    for (int r = 0; r < 8; r++) {
        int mloc = (r >> 2) * 64 + ty * 4 + (r & 3);
        int gm = m0 + mloc;
        if (gm < N_NODES) {
            *reinterpret_cast<float4*>(&g_feat[gm * HID + tx * 4]) =
                make_float4(acc[r][0], acc[r][1], acc[r][2], acc[r][3]);
            *reinterpret_cast<float4*>(&g_feat[gm * HID + 64 + tx * 4]) =
                make_float4(acc[r][4], acc[r][5], acc[r][6], acc[r][7]);
        }
    }
}

// ================= gather: pure weighted aggregation with precomputed alpha =================
__global__ __launch_bounds__(256) void gat_gather_kernel() {
    int warp = (blockIdx.x * blockDim.x + threadIdx.x) >> 5;
    int lane = threadIdx.x & 31;
    if (warp >= N_NODES) return;
    int start = g_row[warp];
    int deg = g_row[warp + 1] - start;
    float4 acc = make_float4(0.f, 0.f, 0.f, 0.f);
    const float4* feat4 = reinterpret_cast<const float4*>(g_feat);
    if (deg > 0 && deg <= 32) {
        // one edge per lane: load alpha + src once, broadcast via shuffle
        int sidx = 0;
        float alpha = 0.f;
        if (lane < deg) {
            sidx = g_csr_src[start + lane];
            alpha = g_alpha[start + lane];
        }
        int j = 0;
        for (; j + 4 <= deg; j += 4) {
            float a0 = __shfl_sync(FULLMASK, alpha, j);
            float a1 = __shfl_sync(FULLMASK, alpha, j + 1);
            float a2 = __shfl_sync(FULLMASK, alpha, j + 2);
            float a3 = __shfl_sync(FULLMASK, alpha, j + 3);
            int t0 = __shfl_sync(FULLMASK, sidx, j);
            int t1 = __shfl_sync(FULLMASK, sidx, j + 1);
            int t2 = __shfl_sync(FULLMASK, sidx, j + 2);
            int t3 = __shfl_sync(FULLMASK, sidx, j + 3);
            float4 f0 = feat4[t0 * 32 + lane];
            float4 f1 = feat4[t1 * 32 + lane];
            float4 f2 = feat4[t2 * 32 + lane];
            float4 f3 = feat4[t3 * 32 + lane];
            acc.x += a0 * f0.x + a1 * f1.x + a2 * f2.x + a3 * f3.x;
            acc.y += a0 * f0.y + a1 * f1.y + a2 * f2.y + a3 * f3.y;
            acc.z += a0 * f0.z + a1 * f1.z + a2 * f2.z + a3 * f3.z;
            acc.w += a0 * f0.w + a1 * f1.w + a2 * f2.w + a3 * f3.w;
        }
        for (; j < deg; j++) {
            float a0 = __shfl_sync(FULLMASK, alpha, j);
            int t0 = __shfl_sync(FULLMASK, sidx, j);
            float4 f0 = feat4[t0 * 32 + lane];
            acc.x += a0 * f0.x;
            acc.y += a0 * f0.y;
            acc.z += a0 * f0.z;
            acc.w += a0 * f0.w;
        }
    } else if (deg > 32) {
        int end = start + deg;
        int i = start;
        for (; i + 1 < end; i += 2) {
            int s0 = g_csr_src[i];
            int s1 = g_csr_src[i + 1];
            float a0 = g_alpha[i];
            float a1 = g_alpha[i + 1];
            float4 f0 = feat4[s0 * 32 + lane];
            float4 f1 = feat4[s1 * 32 + lane];
            acc.x += a0 * f0.x + a1 * f1.x;
            acc.y += a0 * f0.y + a1 * f1.y;
            acc.z += a0 * f0.z + a1 * f1.z;
            acc.w += a0 * f0.w + a1 * f1.w;
        }
        if (i < end) {
            int s0 = g_csr_src[i];
            float a0 = g_alpha[i];
            float4 f0 = feat4[s0 * 32 + lane];
            acc.x += a0 * f0.x;
            acc.y += a0 * f0.y;
            acc.z += a0 * f0.z;
            acc.w += a0 * f0.w;
        }
    }
    reinterpret_cast<float4*>(g_agg)[warp * 32 + lane] = acc;
}

// ================= GEMM2: out = leaky(agg + bias) @ W_lin^T =================
__global__ __launch_bounds__(256) void gemm_out_kernel(
    const float* __restrict__ Wl, const float* __restrict__ bias,
    float* __restrict__ out) {
    __shared__ __align__(16) float Wt[HID][66];
    __shared__ __align__(16) float At[16][136];
    const int tid = threadIdx.x;
    const int tx = tid & 15;
    const int ty = tid >> 4;
    const int r0 = blockIdx.x * 128;

    for (int i = tid; i < OUT_F * (HID / 4); i += 256) {
        int o = i >> 5;
        int k4 = i & 31;
        float4 w = *reinterpret_cast<const float4*>(&Wl[o * HID + k4 * 4]);
        Wt[k4 * 4 + 0][o] = w.x;
        Wt[k4 * 4 + 1][o] = w.y;
        Wt[k4 * 4 + 2][o] = w.z;
        Wt[k4 * 4 + 3][o] = w.w;
    }

    float acc[8][4];
#pragma unroll
    for (int i = 0; i < 8; i++)
#pragma unroll
        for (int j = 0; j < 4; j++) acc[i][j] = 0.f;

    const int lrow = tid >> 2;
    const int kq = tid & 3;
    for (int c = 0; c < HID / 16; ++c) {
        int k0 = c * 16;
        __syncthreads();
        float4 bb = *reinterpret_cast<const float4*>(&bias[k0 + kq * 4]);
#pragma unroll
        for (int p = 0; p < 2; ++p) {
            int row = lrow + p * 64;
            int gr = r0 + row;
            float4 v = make_float4(0.f, 0.f, 0.f, 0.f);
            if (gr < N_NODES) {
                v = *reinterpret_cast<const float4*>(&g_agg[gr * HID + k0 + kq * 4]);
                v.x += bb.x; v.y += bb.y; v.z += bb.z; v.w += bb.w;
                v.x = (v.x > 0.f) ? v.x : ACT_SLOPE * v.x;
                v.y = (v.y > 0.f) ? v.y : ACT_SLOPE * v.y;
                v.z = (v.z > 0.f) ? v.z : ACT_SLOPE * v.z;
                v.w = (v.w > 0.f) ? v.w : ACT_SLOPE * v.w;
            }
            At[kq * 4 + 0][row] = v.x;
            At[kq * 4 + 1][row] = v.y;
            At[kq * 4 + 2][row] = v.z;
            At[kq * 4 + 3][row] = v.w;
        }
        __syncthreads();
#pragma unroll
        for (int k = 0; k < 16; ++k) {
            float a[8];
            *reinterpret_cast<float4*>(&a[0]) =
                *reinterpret_cast<const float4*>(&At[k][ty * 8]);
            *reinterpret_cast<float4*>(&a[4]) =
                *reinterpret_cast<const float4*>(&At[k][ty * 8 + 4]);
            float b0 = Wt[k0 + k][tx * 4 + 0];
            float b1 = Wt[k0 + k][tx * 4 + 1];
            float b2 = Wt[k0 + k][tx * 4 + 2];
            float b3 = Wt[k0 + k][tx * 4 + 3];
#pragma unroll
            for (int i = 0; i < 8; i++) {
                acc[i][0] += a[i] * b0;
                acc[i][1] += a[i] * b1;
                acc[i][2] += a[i] * b2;
                acc[i][3] += a[i] * b3;
            }
        }
    }
#pragma unroll
    for (int i = 0; i < 8; i++) {
        int gr = r0 + ty * 8 + i;
        if (gr < N_NODES) {
            *reinterpret_cast<float4*>(&out[gr * OUT_F + tx * 4]) =
                make_float4(acc[i][0], acc[i][1], acc[i][2], acc[i][3]);
        }
    }
}

// ================= stream/event fork-join for captured-graph overlap =================
namespace {
struct SideResources {
    cudaStream_t side;
    cudaEvent_t fork, join;
    SideResources() {
        cudaStreamCreateWithFlags(&side, cudaStreamNonBlocking);
        cudaEventCreateWithFlags(&fork, cudaEventDisableTiming);
        cudaEventCreateWithFlags(&join, cudaEventDisableTiming);
    }
};
}  // namespace

// ================= launch =================
extern "C" void kernel_launch(void* const* d_in, const int* in_sizes, int n_in,
                              void* d_out, int out_size) {
    static SideResources R;

    const float* x       = (const float*)d_in[0];
    const int*   src     = (const int*)d_in[1];
    const int*   dst     = (const int*)d_in[2];
    const float* W_gat   = (const float*)d_in[3];
    const float* attn_l  = (const float*)d_in[4];
    const float* attn_r  = (const float*)d_in[5];
    const float* bias    = (const float*)d_in[6];
    const float* W_lin   = (const float*)d_in[7];
    float* out = (float*)d_out;

    // Fork: full attention-softmax chain on side stream; GEMM1 on main stream.
    cudaEventRecord(R.fork, 0);
    cudaStreamWaitEvent(R.side, R.fork, 0);

    init_cnt_kernel<<<64, 256, 0, R.side>>>();
    hist_kernel<<<(N_EDGES + 255) / 256, 256, 0, R.side>>>(dst);
    wlr_kernel<<<(IN_F * 32 + 255) / 256, 256, 0, R.side>>>(W_gat, attn_l, attn_r);
    elr_kernel<<<(N_NODES * 32 + 255) / 256, 256, 0, R.side>>>(x);
    scan_kernel<<<1, 1024, 0, R.side>>>();
    scatter_kernel<<<(N_EDGES + 255) / 256, 256, 0, R.side>>>(src, dst);
    edge_softmax_kernel<<<(N_NODES * 32 + 255) / 256, 256, 0, R.side>>>();
    cudaEventRecord(R.join, R.side);

    gemm_feat_kernel<<<(N_NODES + 127) / 128, 256>>>(x, W_gat);

    // Join: gather needs feat (main) + alpha/CSR (side).
    cudaStreamWaitEvent(0, R.join, 0);

    gat_gather_kernel<<<(N_NODES * 32 + 255) / 256, 256>>>();
    gemm_out_kernel<<<(N_NODES + 127) / 128, 256>>>(W_lin, bias, out);
}

// round 6
// speedup vs baseline: 1.1250x; 1.1250x over previous
#include <cuda_runtime.h>
#include <cuda_fp16.h>

#define N_NODES 50000
#define N_EDGES 800000
#define IN_F 256
#define HID 128
#define OUT_F 64
#define ATTN_SLOPE 0.2f
#define ACT_SLOPE 0.01f
#define NEG_BIG -1.0e30f
#define FULLMASK 0xFFFFFFFFu

// -------- scratch (device globals; no allocation allowed) --------
__device__ __half g_feat_h[N_NODES * HID];   // x @ W_gat, fp16 (gather path)
__device__ float g_el[N_NODES];
__device__ float g_er[N_NODES];
__device__ float g_agg[N_NODES * HID];
__device__ int   g_cnt[N_NODES];
__device__ int   g_row[N_NODES + 1];
__device__ int   g_cursor[N_NODES];
__device__ int   g_csr_src[N_EDGES];

// ================= zero the histogram =================
__global__ void init_cnt_kernel() {
    int tid = blockIdx.x * blockDim.x + threadIdx.x;
    int stride = gridDim.x * blockDim.x;
    for (int i = tid; i < N_NODES; i += stride) g_cnt[i] = 0;
}

// ================= histogram of dst =================
__global__ __launch_bounds__(256) void hist_kernel(const int* __restrict__ dst) {
    int i = blockIdx.x * blockDim.x + threadIdx.x;
    if (i < N_EDGES) atomicAdd(&g_cnt[dst[i]], 1);
}

// ================= single-block exclusive scan over 50000 counts =================
__global__ __launch_bounds__(1024) void scan_kernel() {
    __shared__ int sm[1024];
    const int CH = (N_NODES + 1023) / 1024;  // 49
    int tid = threadIdx.x;
    int base = tid * CH;
    int local[49];
    int sum = 0;
#pragma unroll
    for (int j = 0; j < CH; j++) {
        int idx = base + j;
        int c = (idx < N_NODES) ? g_cnt[idx] : 0;
        local[j] = c;
        sum += c;
    }
    sm[tid] = sum;
    __syncthreads();
    for (int off = 1; off < 1024; off <<= 1) {
        int v = sm[tid];
        if (tid >= off) v += sm[tid - off];
        __syncthreads();
        sm[tid] = v;
        __syncthreads();
    }
    int run = (tid > 0) ? sm[tid - 1] : 0;
#pragma unroll
    for (int j = 0; j < CH; j++) {
        int idx = base + j;
        if (idx < N_NODES) {
            g_row[idx] = run;
            g_cursor[idx] = run;
            run += local[j];
        }
    }
    if (tid == 1023) g_row[N_NODES] = N_EDGES;
}

// ================= scatter edges into CSR buckets =================
__global__ __launch_bounds__(256) void scatter_kernel(
    const int* __restrict__ src, const int* __restrict__ dst) {
    int i = blockIdx.x * blockDim.x + threadIdx.x;
    if (i >= N_EDGES) return;
    int d = dst[i];
    int pos = atomicAdd(&g_cursor[d], 1);
    g_csr_src[pos] = src[i];
}

// ================= GEMM1 + attn epilogue (feat stored fp16, el/er fp32) =================
__global__ __launch_bounds__(256) void gemm_feat_attn_kernel(
    const float* __restrict__ x, const float* __restrict__ W,
    const float* __restrict__ al, const float* __restrict__ ar) {
    __shared__ __align__(16) float As[2][8][132];
    __shared__ __align__(16) float Bs[2][8][128];
    __shared__ float red_l[16][130];
    __shared__ float red_r[16][130];
    const int m0 = blockIdx.x * 128;
    const int tid = threadIdx.x;
    const int tx = tid & 15;
    const int ty = tid >> 4;
    const int arow = tid >> 1;
    const int ac4  = tid & 1;
    const int brow = tid >> 5;
    const int bc4  = tid & 31;

    float4 a_reg, b_reg;
    {
        int gm = m0 + arow;
        a_reg = (gm < N_NODES)
            ? *reinterpret_cast<const float4*>(&x[gm * IN_F + ac4 * 4])
            : make_float4(0.f, 0.f, 0.f, 0.f);
        b_reg = *reinterpret_cast<const float4*>(&W[brow * HID + bc4 * 4]);
    }
    As[0][ac4 * 4 + 0][arow] = a_reg.x;
    As[0][ac4 * 4 + 1][arow] = a_reg.y;
    As[0][ac4 * 4 + 2][arow] = a_reg.z;
    As[0][ac4 * 4 + 3][arow] = a_reg.w;
    *reinterpret_cast<float4*>(&Bs[0][brow][bc4 * 4]) = b_reg;
    __syncthreads();

    float acc[8][8];
#pragma unroll
    for (int i = 0; i < 8; i++)
#pragma unroll
        for (int j = 0; j < 8; j++) acc[i][j] = 0.f;

    int cur = 0;
    for (int t = 0; t < IN_F / 8; ++t) {
        if (t + 1 < IN_F / 8) {
            int k0 = (t + 1) * 8;
            int gm = m0 + arow;
            a_reg = (gm < N_NODES)
                ? *reinterpret_cast<const float4*>(&x[gm * IN_F + k0 + ac4 * 4])
                : make_float4(0.f, 0.f, 0.f, 0.f);
            b_reg = *reinterpret_cast<const float4*>(&W[(k0 + brow) * HID + bc4 * 4]);
        }
#pragma unroll
        for (int k = 0; k < 8; ++k) {
            float a[8], b[8];
            *reinterpret_cast<float4*>(&a[0]) =
                *reinterpret_cast<const float4*>(&As[cur][k][ty * 4]);
            *reinterpret_cast<float4*>(&a[4]) =
                *reinterpret_cast<const float4*>(&As[cur][k][64 + ty * 4]);
            *reinterpret_cast<float4*>(&b[0]) =
                *reinterpret_cast<const float4*>(&Bs[cur][k][tx * 4]);
            *reinterpret_cast<float4*>(&b[4]) =
                *reinterpret_cast<const float4*>(&Bs[cur][k][64 + tx * 4]);
#pragma unroll
            for (int i = 0; i < 8; i++)
#pragma unroll
                for (int j = 0; j < 8; j++) acc[i][j] += a[i] * b[j];
        }
        if (t + 1 < IN_F / 8) {
            int nxt = cur ^ 1;
            As[nxt][ac4 * 4 + 0][arow] = a_reg.x;
            As[nxt][ac4 * 4 + 1][arow] = a_reg.y;
            As[nxt][ac4 * 4 + 2][arow] = a_reg.z;
            As[nxt][ac4 * 4 + 3][arow] = a_reg.w;
            *reinterpret_cast<float4*>(&Bs[nxt][brow][bc4 * 4]) = b_reg;
            __syncthreads();
            cur = nxt;
        }
    }

    float alv[8], arv[8];
    {
        float4 a0 = *reinterpret_cast<const float4*>(&al[tx * 4]);
        float4 a1 = *reinterpret_cast<const float4*>(&al[64 + tx * 4]);
        float4 r0 = *reinterpret_cast<const float4*>(&ar[tx * 4]);
        float4 r1 = *reinterpret_cast<const float4*>(&ar[64 + tx * 4]);
        alv[0] = a0.x; alv[1] = a0.y; alv[2] = a0.z; alv[3] = a0.w;
        alv[4] = a1.x; alv[5] = a1.y; alv[6] = a1.z; alv[7] = a1.w;
        arv[0] = r0.x; arv[1] = r0.y; arv[2] = r0.z; arv[3] = r0.w;
        arv[4] = r1.x; arv[5] = r1.y; arv[6] = r1.z; arv[7] = r1.w;
    }
#pragma unroll
    for (int r = 0; r < 8; r++) {
        int mloc = (r >> 2) * 64 + ty * 4 + (r & 3);
        int gm = m0 + mloc;
        float pl = 0.f, pr = 0.f;
#pragma unroll
        for (int c = 0; c < 8; c++) {
            pl += acc[r][c] * alv[c];
            pr += acc[r][c] * arv[c];
        }
        red_l[tx][mloc] = pl;
        red_r[tx][mloc] = pr;
        if (gm < N_NODES) {
            // fp16 feat: 4 halfs (8B) at col tx*4 and 64+tx*4
            __half2 p0 = __float22half2_rn(make_float2(acc[r][0], acc[r][1]));
            __half2 p1 = __float22half2_rn(make_float2(acc[r][2], acc[r][3]));
            __half2 p2 = __float22half2_rn(make_float2(acc[r][4], acc[r][5]));
            __half2 p3 = __float22half2_rn(make_float2(acc[r][6], acc[r][7]));
            *reinterpret_cast<__half2*>(&g_feat_h[gm * HID + tx * 4])     = p0;
            *reinterpret_cast<__half2*>(&g_feat_h[gm * HID + tx * 4 + 2]) = p1;
            *reinterpret_cast<__half2*>(&g_feat_h[gm * HID + 64 + tx * 4])     = p2;
            *reinterpret_cast<__half2*>(&g_feat_h[gm * HID + 64 + tx * 4 + 2]) = p3;
        }
    }
    __syncthreads();
    if (tid < 128) {
        int gm = m0 + tid;
        float sl = 0.f, sr = 0.f;
#pragma unroll
        for (int t = 0; t < 16; t++) {
            sl += red_l[t][tid];
            sr += red_r[t][tid];
        }
        if (gm < N_NODES) {
            g_el[gm] = sl;
            g_er[gm] = sr;
        }
    }
}

// helper: fp16x4 load -> fp32 accumulate
__device__ __forceinline__ void fma_feat(float4& acc, float a, uint2 u) {
    __half2 h0 = *reinterpret_cast<__half2*>(&u.x);
    __half2 h1 = *reinterpret_cast<__half2*>(&u.y);
    float2 f0 = __half22float2(h0);
    float2 f1 = __half22float2(h1);
    acc.x += a * f0.x;
    acc.y += a * f0.y;
    acc.z += a * f1.x;
    acc.w += a * f1.y;
}

// ================= fused gather: per-node softmax + weighted aggregation (fp16 feat) =================
__global__ __launch_bounds__(256) void gat_gather_kernel() {
    int warp = (blockIdx.x * blockDim.x + threadIdx.x) >> 5;
    int lane = threadIdx.x & 31;
    if (warp >= N_NODES) return;
    int start = g_row[warp];
    int deg = g_row[warp + 1] - start;
    float4 acc = make_float4(0.f, 0.f, 0.f, 0.f);
    const uint2* feat8 = reinterpret_cast<const uint2*>(g_feat_h);  // 4 halfs per unit
    if (deg > 0) {
        float er_d = g_er[warp];
        if (deg <= 32) {
            // ---- one edge per lane ----
            int sidx = 0;
            float e = NEG_BIG;
            if (lane < deg) {
                sidx = g_csr_src[start + lane];
                float v = g_el[sidx] + er_d;
                e = (v > 0.f) ? v : ATTN_SLOPE * v;
            }
            float m = e;
#pragma unroll
            for (int o = 16; o > 0; o >>= 1)
                m = fmaxf(m, __shfl_xor_sync(FULLMASK, m, o));
            float p = (lane < deg) ? __expf(e - m) : 0.f;
            float s = p;
#pragma unroll
            for (int o = 16; o > 0; o >>= 1)
                s += __shfl_xor_sync(FULLMASK, s, o);
            float alpha = p / s;
            int j = 0;
            for (; j + 4 <= deg; j += 4) {
                float a0 = __shfl_sync(FULLMASK, alpha, j);
                float a1 = __shfl_sync(FULLMASK, alpha, j + 1);
                float a2 = __shfl_sync(FULLMASK, alpha, j + 2);
                float a3 = __shfl_sync(FULLMASK, alpha, j + 3);
                int t0 = __shfl_sync(FULLMASK, sidx, j);
                int t1 = __shfl_sync(FULLMASK, sidx, j + 1);
                int t2 = __shfl_sync(FULLMASK, sidx, j + 2);
                int t3 = __shfl_sync(FULLMASK, sidx, j + 3);
                uint2 u0 = feat8[t0 * 32 + lane];
                uint2 u1 = feat8[t1 * 32 + lane];
                uint2 u2 = feat8[t2 * 32 + lane];
                uint2 u3 = feat8[t3 * 32 + lane];
                fma_feat(acc, a0, u0);
                fma_feat(acc, a1, u1);
                fma_feat(acc, a2, u2);
                fma_feat(acc, a3, u3);
            }
            for (; j < deg; j++) {
                float a0 = __shfl_sync(FULLMASK, alpha, j);
                int t0 = __shfl_sync(FULLMASK, sidx, j);
                uint2 u0 = feat8[t0 * 32 + lane];
                fma_feat(acc, a0, u0);
            }
        } else {
            // ---- general path ----
            int end = start + deg;
            float m = NEG_BIG, s = 0.f;
            for (int i = start + lane; i < end; i += 32) {
                int sx = g_csr_src[i];
                float v = g_el[sx] + er_d;
                float e = (v > 0.f) ? v : ATTN_SLOPE * v;
                float nm = fmaxf(m, e);
                s = s * __expf(m - nm) + __expf(e - nm);
                m = nm;
            }
#pragma unroll
            for (int o = 16; o > 0; o >>= 1) {
                float mo = __shfl_xor_sync(FULLMASK, m, o);
                float so = __shfl_xor_sync(FULLMASK, s, o);
                float nm = fmaxf(m, mo);
                s = s * __expf(m - nm) + so * __expf(mo - nm);
                m = nm;
            }
            float inv = 1.f / s;
            int i = start;
            for (; i + 1 < end; i += 2) {
                int s0 = g_csr_src[i];
                int s1 = g_csr_src[i + 1];
                float v0 = g_el[s0] + er_d;
                float v1 = g_el[s1] + er_d;
                float e0 = (v0 > 0.f) ? v0 : ATTN_SLOPE * v0;
                float e1 = (v1 > 0.f) ? v1 : ATTN_SLOPE * v1;
                float a0 = __expf(e0 - m) * inv;
                float a1 = __expf(e1 - m) * inv;
                uint2 u0 = feat8[s0 * 32 + lane];
                uint2 u1 = feat8[s1 * 32 + lane];
                fma_feat(acc, a0, u0);
                fma_feat(acc, a1, u1);
            }
            if (i < end) {
                int s0 = g_csr_src[i];
                float v0 = g_el[s0] + er_d;
                float e0 = (v0 > 0.f) ? v0 : ATTN_SLOPE * v0;
                float a0 = __expf(e0 - m) * inv;
                uint2 u0 = feat8[s0 * 32 + lane];
                fma_feat(acc, a0, u0);
            }
        }
    }
    reinterpret_cast<float4*>(g_agg)[warp * 32 + lane] = acc;
}

// ================= GEMM2: out = leaky(agg + bias) @ W_lin^T =================
__global__ __launch_bounds__(256) void gemm_out_kernel(
    const float* __restrict__ Wl, const float* __restrict__ bias,
    float* __restrict__ out) {
    __shared__ __align__(16) float Wt[HID][66];
    __shared__ __align__(16) float At[16][136];
    const int tid = threadIdx.x;
    const int tx = tid & 15;
    const int ty = tid >> 4;
    const int r0 = blockIdx.x * 128;

    for (int i = tid; i < OUT_F * (HID / 4); i += 256) {
        int o = i >> 5;
        int k4 = i & 31;
        float4 w = *reinterpret_cast<const float4*>(&Wl[o * HID + k4 * 4]);
        Wt[k4 * 4 + 0][o] = w.x;
        Wt[k4 * 4 + 1][o] = w.y;
        Wt[k4 * 4 + 2][o] = w.z;
        Wt[k4 * 4 + 3][o] = w.w;
    }

    float acc[8][4];
#pragma unroll
    for (int i = 0; i < 8; i++)
#pragma unroll
        for (int j = 0; j < 4; j++) acc[i][j] = 0.f;

    const int lrow = tid >> 2;
    const int kq = tid & 3;
    for (int c = 0; c < HID / 16; ++c) {
        int k0 = c * 16;
        __syncthreads();
        float4 bb = *reinterpret_cast<const float4*>(&bias[k0 + kq * 4]);
#pragma unroll
        for (int p = 0; p < 2; ++p) {
            int row = lrow + p * 64;
            int gr = r0 + row;
            float4 v = make_float4(0.f, 0.f, 0.f, 0.f);
            if (gr < N_NODES) {
                v = *reinterpret_cast<const float4*>(&g_agg[gr * HID + k0 + kq * 4]);
                v.x += bb.x; v.y += bb.y; v.z += bb.z; v.w += bb.w;
                v.x = (v.x > 0.f) ? v.x : ACT_SLOPE * v.x;
                v.y = (v.y > 0.f) ? v.y : ACT_SLOPE * v.y;
                v.z = (v.z > 0.f) ? v.z : ACT_SLOPE * v.z;
                v.w = (v.w > 0.f) ? v.w : ACT_SLOPE * v.w;
            }
            At[kq * 4 + 0][row] = v.x;
            At[kq * 4 + 1][row] = v.y;
            At[kq * 4 + 2][row] = v.z;
            At[kq * 4 + 3][row] = v.w;
        }
        __syncthreads();
#pragma unroll
        for (int k = 0; k < 16; ++k) {
            float a[8];
            *reinterpret_cast<float4*>(&a[0]) =
                *reinterpret_cast<const float4*>(&At[k][ty * 8]);
            *reinterpret_cast<float4*>(&a[4]) =
                *reinterpret_cast<const float4*>(&At[k][ty * 8 + 4]);
            float b0 = Wt[k0 + k][tx * 4 + 0];
            float b1 = Wt[k0 + k][tx * 4 + 1];
            float b2 = Wt[k0 + k][tx * 4 + 2];
            float b3 = Wt[k0 + k][tx * 4 + 3];
#pragma unroll
            for (int i = 0; i < 8; i++) {
                acc[i][0] += a[i] * b0;
                acc[i][1] += a[i] * b1;
                acc[i][2] += a[i] * b2;
                acc[i][3] += a[i] * b3;
            }
        }
    }
#pragma unroll
    for (int i = 0; i < 8; i++) {
        int gr = r0 + ty * 8 + i;
        if (gr < N_NODES) {
            *reinterpret_cast<float4*>(&out[gr * OUT_F + tx * 4]) =
                make_float4(acc[i][0], acc[i][1], acc[i][2], acc[i][3]);
        }
    }
}

// ================= stream/event fork-join for captured-graph overlap =================
namespace {
struct SideResources {
    cudaStream_t side;
    cudaEvent_t fork, join;
    SideResources() {
        cudaStreamCreateWithFlags(&side, cudaStreamNonBlocking);
        cudaEventCreateWithFlags(&fork, cudaEventDisableTiming);
        cudaEventCreateWithFlags(&join, cudaEventDisableTiming);
    }
};
}  // namespace

// ================= launch =================
extern "C" void kernel_launch(void* const* d_in, const int* in_sizes, int n_in,
                              void* d_out, int out_size) {
    static SideResources R;

    const float* x       = (const float*)d_in[0];
    const int*   src     = (const int*)d_in[1];
    const int*   dst     = (const int*)d_in[2];
    const float* W_gat   = (const float*)d_in[3];
    const float* attn_l  = (const float*)d_in[4];
    const float* attn_r  = (const float*)d_in[5];
    const float* bias    = (const float*)d_in[6];
    const float* W_lin   = (const float*)d_in[7];
    float* out = (float*)d_out;

    // Fork: CSR build on side stream; GEMM1+attn on main stream.
    cudaEventRecord(R.fork, 0);
    cudaStreamWaitEvent(R.side, R.fork, 0);

    init_cnt_kernel<<<64, 256, 0, R.side>>>();
    hist_kernel<<<(N_EDGES + 255) / 256, 256, 0, R.side>>>(dst);
    scan_kernel<<<1, 1024, 0, R.side>>>();
    scatter_kernel<<<(N_EDGES + 255) / 256, 256, 0, R.side>>>(src, dst);
    cudaEventRecord(R.join, R.side);

    gemm_feat_attn_kernel<<<(N_NODES + 127) / 128, 256>>>(x, W_gat, attn_l, attn_r);

    // Join: gather needs CSR (side) + feat/el/er (main).
    cudaStreamWaitEvent(0, R.join, 0);

    gat_gather_kernel<<<(N_NODES * 32 + 255) / 256, 256>>>();
    gemm_out_kernel<<<(N_NODES + 127) / 128, 256>>>(W_lin, bias, out);
}